// round 11
// baseline (speedup 1.0000x reference)
#include <cuda_runtime.h>
#include <cuda_fp16.h>
#include <math.h>

#define BB 2
#define NN 20000
#define EE 320000
#define DD 128
#define ROWS (BB*NN)          // 40000, divisible by TM
#define TM 64
#define APITCH 68
#define BPITCH 132
#define SMEM_BYTES ((128*APITCH + 128*BPITCH)*4)   // 102400 bytes -> 2 CTAs/SM

// ---- scratch (device globals; no allocation allowed) ----
__device__ __half2 g_hh[ROWS*64];   // h in fp16 (row-major, 64 half2 per row)  10 MB
__device__ float g_w[ROWS];         // exp(alpha) per node
__device__ float g_P[ROWS*DD];      // softmax-weighted mean of h  (per dst)
__device__ float g_S[ROWS*DD];      // plain mean of h             (per dst)
__device__ float g_M[DD*DD];        // Wq @ Wk^T
__device__ float g_u[DD];           // Wq bk + Wk bq
__device__ float g_c;               // bq . bk
__device__ int   g_counts[NN];
__device__ int   g_offsets[NN+1];
__device__ int   g_cursor[NN];
__device__ int   g_srcsorted[EE];   // src ids grouped by dst (CSR)

// ======================= precompute: M = Wq Wk^T, u, c =======================
// alpha_i = 0.25 * ( h_i M h_i^T + h_i . u + c )

__global__ __launch_bounds__(128)
void precompute_kernel(const float* __restrict__ Wq, const float* __restrict__ bq,
                       const float* __restrict__ Wk, const float* __restrict__ bk) {
    __shared__ float wq_row[128];
    __shared__ float red[128];
    const int k = blockIdx.x;
    const int l = threadIdx.x;

    wq_row[l] = Wq[k*128 + l];
    __syncthreads();

    const float* __restrict__ wkr = Wk + l*128;
    float acc = 0.f;
#pragma unroll 8
    for (int j = 0; j < 128; ++j)
        acc += wq_row[j] * __ldg(wkr + j);
    g_M[k*128 + l] = acc;   // M[k][l] = dot(Wq row k, Wk row l)

    red[l] = wq_row[l] * bk[l] + Wk[k*128 + l] * bq[l];
    __syncthreads();
    for (int off = 64; off; off >>= 1) {
        if (l < off) red[l] += red[l + off];
        __syncthreads();
    }
    if (l == 0) g_u[k] = red[0];

    if (k == 0) {
        __syncthreads();
        red[l] = bq[l] * bk[l];
        __syncthreads();
        for (int off = 64; off; off >>= 1) {
            if (l < off) red[l] += red[l + off];
            __syncthreads();
        }
        if (l == 0) g_c = red[0];
    }
}

// ======================= shared GEMM pieces =======================

__device__ __forceinline__ void gemm64(const float* __restrict__ A,
                                       const float* __restrict__ Bs,
                                       float acc[4][8], int ty4, int tx8) {
#pragma unroll 4
    for (int kk = 0; kk < 128; ++kk) {
        const float4 a0 = *reinterpret_cast<const float4*>(A + kk*APITCH + ty4);
        const float4 b0 = *reinterpret_cast<const float4*>(Bs + kk*BPITCH + tx8);
        const float4 b1 = *reinterpret_cast<const float4*>(Bs + kk*BPITCH + tx8 + 4);
        float av[4] = {a0.x, a0.y, a0.z, a0.w};
        float bw[8] = {b0.x, b0.y, b0.z, b0.w, b1.x, b1.y, b1.z, b1.w};
#pragma unroll
        for (int r = 0; r < 4; ++r)
#pragma unroll
            for (int c = 0; c < 8; ++c)
                acc[r][c] += av[r] * bw[c];
    }
}

__device__ __forceinline__ void load_w(const float* __restrict__ W, float* Bs, int tid) {
    for (int idx = tid; idx < DD*DD; idx += 256)
        Bs[(idx >> 7)*BPITCH + (idx & 127)] = W[idx];
}

// ======================= node phase: h, alpha -> fp16 h + exp(alpha) ==========

__global__ __launch_bounds__(256, 2)
void node_kernel(const float* __restrict__ x, const float* __restrict__ Wp) {
    extern __shared__ float sm[];
    float* A  = sm;                 // 128(k) x APITCH : x^T then h^T
    float* Bs = sm + 128*APITCH;    // 128 x BPITCH   : weight matrix
    __shared__ float alpha_sh[TM];

    const int tid = threadIdx.x;
    const int tx  = tid & 15, ty = tid >> 4;
    const int tx8 = tx * 8,  ty4 = ty * 4;
    const int row0 = blockIdx.x * TM;      // ROWS % TM == 0 -> no bounds checks

    if (tid < TM) alpha_sh[tid] = g_c;

    // load x^T and Wp
    for (int idx = tid; idx < TM*DD; idx += 256) {
        int m = idx >> 7, k = idx & 127;
        A[k*APITCH + m] = x[(size_t)(row0 + m)*DD + k];
    }
    load_w(Wp, Bs, tid);
    __syncthreads();

    float acc[4][8];
#pragma unroll
    for (int r = 0; r < 4; ++r)
#pragma unroll
        for (int c = 0; c < 8; ++c) acc[r][c] = 0.f;
    gemm64(A, Bs, acc, ty4, tx8);          // acc = h tile
    __syncthreads();

    // keep h in registers, store h^T into A; stage M
    float hreg[4][8];
#pragma unroll
    for (int r = 0; r < 4; ++r)
#pragma unroll
        for (int c = 0; c < 8; ++c) {
            hreg[r][c] = acc[r][c];
            A[(tx8 + c)*APITCH + ty4 + r] = acc[r][c];
        }
    load_w(g_M, Bs, tid);
    __syncthreads();

    // store h as fp16 (row-major half2), straight from registers
#pragma unroll
    for (int r = 0; r < 4; ++r) {
        size_t base = (size_t)(row0 + ty4 + r) * 64 + tx * 4;
#pragma unroll
        for (int j = 0; j < 4; ++j)
            g_hh[base + j] = __floats2half2_rn(hreg[r][2*j], hreg[r][2*j + 1]);
    }

    // t = h @ M ; alpha += (t + u) . h
#pragma unroll
    for (int r = 0; r < 4; ++r)
#pragma unroll
        for (int c = 0; c < 8; ++c) acc[r][c] = 0.f;
    gemm64(A, Bs, acc, ty4, tx8);
    {
        float4 u0 = *reinterpret_cast<const float4*>(g_u + tx8);
        float4 u1 = *reinterpret_cast<const float4*>(g_u + tx8 + 4);
        float ub[8] = {u0.x,u0.y,u0.z,u0.w,u1.x,u1.y,u1.z,u1.w};
#pragma unroll
        for (int r = 0; r < 4; ++r) {
            float p = 0.f;
#pragma unroll
            for (int c = 0; c < 8; ++c) p += (acc[r][c] + ub[c]) * hreg[r][c];
            atomicAdd(&alpha_sh[ty4 + r], p);
        }
    }
    __syncthreads();
    if (tid < TM)
        g_w[row0 + tid] = __expf(alpha_sh[tid] * 0.25f);   // scale = 1/sqrt(16)
}

// ======================= CSR build =======================

__global__ void zero_counts_kernel() {
    int i = blockIdx.x * blockDim.x + threadIdx.x;
    if (i < NN) g_counts[i] = 0;
}

__global__ void hist_kernel(const int* __restrict__ dst) {
    int e = blockIdx.x * blockDim.x + threadIdx.x;
    if (e < EE) atomicAdd(&g_counts[dst[e]], 1);
}

__global__ __launch_bounds__(1024)
void scan_kernel() {
    __shared__ int wsum[32];
    const int tid = threadIdx.x, lane = tid & 31, wid = tid >> 5;
    const int C = 20;
    const int base = tid * C;
    int loc[C];
    int s = 0;
#pragma unroll
    for (int i = 0; i < C; ++i) {
        int idx = base + i;
        int v = (idx < NN) ? g_counts[idx] : 0;
        loc[i] = s; s += v;
    }
    int inc = s;
#pragma unroll
    for (int off = 1; off < 32; off <<= 1) {
        int t = __shfl_up_sync(0xffffffffu, inc, off);
        if (lane >= off) inc += t;
    }
    if (lane == 31) wsum[wid] = inc;
    __syncthreads();
    if (wid == 0) {
        int w = wsum[lane];
#pragma unroll
        for (int off = 1; off < 32; off <<= 1) {
            int t = __shfl_up_sync(0xffffffffu, w, off);
            if (lane >= off) w += t;
        }
        wsum[lane] = w;
    }
    __syncthreads();
    int excl = (wid ? wsum[wid-1] : 0) + inc - s;
#pragma unroll
    for (int i = 0; i < C; ++i) {
        int idx = base + i;
        if (idx < NN) { int e = excl + loc[i]; g_offsets[idx] = e; g_cursor[idx] = e; }
    }
    if (tid == 0) g_offsets[NN] = wsum[31];
}

__global__ void scatter_kernel(const int* __restrict__ src, const int* __restrict__ dst) {
    int e = blockIdx.x * blockDim.x + threadIdx.x;
    if (e < EE) {
        int d = dst[e];
        int pos = atomicAdd(&g_cursor[d], 1);
        g_srcsorted[pos] = src[e];
    }
}

// ========== per-dst aggregation: P = softmax-weighted mean(h), S = mean(h) =====

__global__ __launch_bounds__(256)
void agg_kernel() {
    const int gw   = blockIdx.x * 8 + (threadIdx.x >> 5);   // (b, node)
    const int lane = threadIdx.x & 31;
    if (gw >= ROWS) return;
    const int b = (gw >= NN) ? 1 : 0;
    const int n = gw - b * NN;

    const int off = g_offsets[n];
    const int cnt = g_offsets[n + 1] - off;
    const float* __restrict__ w_b = g_w + b * NN;
    const uint2* __restrict__ hp  = reinterpret_cast<const uint2*>(g_hh) + (size_t)b * NN * 32;

    float a0=0.f,a1=0.f,a2=0.f,a3=0.f;      // weighted accumulation
    float h0=0.f,h1=0.f,h2=0.f,h3=0.f;      // plain accumulation
    float wsum_l = 0.f;

    for (int c0 = 0; c0 < cnt; c0 += 32) {
        int rem = cnt - c0; if (rem > 32) rem = 32;
        int   s_l = 0;
        float w_l = 0.f;
        if (lane < rem) {
            s_l = g_srcsorted[off + c0 + lane];
            w_l = w_b[s_l];
        }
        wsum_l += w_l;
#pragma unroll 4
        for (int jj = 0; jj < rem; ++jj) {
            int   s = __shfl_sync(0xffffffffu, s_l, jj);
            float w = __shfl_sync(0xffffffffu, w_l, jj);
            // lane owns dims 4*lane .. 4*lane+3 : one uint2 = 4 halves
            uint2 raw = hp[(size_t)s * 32 + lane];
            float2 f01 = __half22float2(*reinterpret_cast<const __half2*>(&raw.x));
            float2 f23 = __half22float2(*reinterpret_cast<const __half2*>(&raw.y));
            a0 += w*f01.x; a1 += w*f01.y; a2 += w*f23.x; a3 += w*f23.y;
            h0 += f01.x;   h1 += f01.y;   h2 += f23.x;   h3 += f23.y;
        }
    }

    float ssum = wsum_l;
#pragma unroll
    for (int o = 16; o; o >>= 1) ssum += __shfl_xor_sync(0xffffffffu, ssum, o);

    const float invs = (cnt > 0) ? (1.f / ssum) : 0.f;
    const float invc = 1.f / fmaxf((float)cnt, 1.f);

    float4 P; P.x = a0*invs; P.y = a1*invs; P.z = a2*invs; P.w = a3*invs;
    float4 S; S.x = h0*invc; S.y = h1*invc; S.z = h2*invc; S.w = h3*invc;
    *reinterpret_cast<float4*>(g_P + (size_t)gw*DD + lane*4) = P;
    *reinterpret_cast<float4*>(g_S + (size_t)gw*DD + lane*4) = S;
}

// ========== post: out = LN( P@Wv + bv + S ) =====================================

__global__ __launch_bounds__(256, 2)
void post_kernel(const float* __restrict__ Wv, const float* __restrict__ bv,
                 const float* __restrict__ lng, const float* __restrict__ lnb,
                 float* __restrict__ out) {
    extern __shared__ float sm[];
    float* A  = sm;                 // P^T tile
    float* Bs = sm + 128*APITCH;    // Wv
    __shared__ float sh_sum[TM];
    __shared__ float sh_sq[TM];

    const int tid = threadIdx.x;
    const int tx  = tid & 15, ty = tid >> 4;
    const int tx8 = tx * 8,  ty4 = ty * 4;
    const int row0 = blockIdx.x * TM;

    if (tid < TM) { sh_sum[tid] = 0.f; sh_sq[tid] = 0.f; }

    for (int idx = tid; idx < TM*DD; idx += 256) {
        int m = idx >> 7, k = idx & 127;
        A[k*APITCH + m] = g_P[(size_t)(row0 + m)*DD + k];
    }
    load_w(Wv, Bs, tid);
    __syncthreads();

    float acc[4][8];
#pragma unroll
    for (int r = 0; r < 4; ++r)
#pragma unroll
        for (int c = 0; c < 8; ++c) acc[r][c] = 0.f;
    gemm64(A, Bs, acc, ty4, tx8);

    // epilogue: + bv + S, cnt==0 guard, LN partials
    float4 b0 = *reinterpret_cast<const float4*>(bv + tx8);
    float4 b1 = *reinterpret_cast<const float4*>(bv + tx8 + 4);
    float bb[8] = {b0.x,b0.y,b0.z,b0.w,b1.x,b1.y,b1.z,b1.w};

#pragma unroll
    for (int r = 0; r < 4; ++r) {
        const int row = row0 + ty4 + r;
        const int n   = (row >= NN) ? row - NN : row;
        const int cnt = g_offsets[n + 1] - g_offsets[n];
        float4 s0 = *reinterpret_cast<const float4*>(g_S + (size_t)row*DD + tx8);
        float4 s1 = *reinterpret_cast<const float4*>(g_S + (size_t)row*DD + tx8 + 4);
        float ss[8] = {s0.x,s0.y,s0.z,s0.w,s1.x,s1.y,s1.z,s1.w};
        float psum = 0.f, psq = 0.f;
#pragma unroll
        for (int c = 0; c < 8; ++c) {
            float v = (cnt > 0) ? (acc[r][c] + bb[c] + ss[c]) : 0.f;
            acc[r][c] = v;
            psum += v;
            psq  += v * v;
        }
        atomicAdd(&sh_sum[ty4 + r], psum);
        atomicAdd(&sh_sq [ty4 + r], psq);
    }
    __syncthreads();

    float4 g0 = *reinterpret_cast<const float4*>(lng + tx8);
    float4 g1 = *reinterpret_cast<const float4*>(lng + tx8 + 4);
    float4 e0 = *reinterpret_cast<const float4*>(lnb + tx8);
    float4 e1 = *reinterpret_cast<const float4*>(lnb + tx8 + 4);
    float gg[8] = {g0.x,g0.y,g0.z,g0.w,g1.x,g1.y,g1.z,g1.w};
    float eb[8] = {e0.x,e0.y,e0.z,e0.w,e1.x,e1.y,e1.z,e1.w};

#pragma unroll
    for (int r = 0; r < 4; ++r) {
        const int row = row0 + ty4 + r;
        const float mean = sh_sum[ty4 + r] * (1.f/128.f);
        const float var  = sh_sq [ty4 + r] * (1.f/128.f) - mean*mean;
        const float rs   = rsqrtf(var + 1e-5f);
        float res[8];
#pragma unroll
        for (int c = 0; c < 8; ++c)
            res[c] = (acc[r][c] - mean) * rs * gg[c] + eb[c];
        float4 w0 = {res[0],res[1],res[2],res[3]};
        float4 w1 = {res[4],res[5],res[6],res[7]};
        *reinterpret_cast<float4*>(out + (size_t)row*DD + tx8)     = w0;
        *reinterpret_cast<float4*>(out + (size_t)row*DD + tx8 + 4) = w1;
    }
}

// ======================= launch =======================

extern "C" void kernel_launch(void* const* d_in, const int* in_sizes, int n_in,
                              void* d_out, int out_size) {
    const float* x    = (const float*)d_in[0];
    const float* Wp   = (const float*)d_in[1];
    const float* Wq   = (const float*)d_in[2];
    const float* bq   = (const float*)d_in[3];
    const float* Wk   = (const float*)d_in[4];
    const float* bk   = (const float*)d_in[5];
    const float* Wv   = (const float*)d_in[6];
    const float* bv   = (const float*)d_in[7];
    const float* lng  = (const float*)d_in[8];
    const float* lnb  = (const float*)d_in[9];
    const int*   ei   = (const int*)d_in[10];
    const int*   src  = ei;
    const int*   dst  = ei + EE;
    float* out = (float*)d_out;

    static cudaStream_t sB = nullptr;
    static cudaEvent_t evFork = nullptr, evJoin = nullptr;
    if (!sB) {
        cudaStreamCreateWithFlags(&sB, cudaStreamNonBlocking);
        cudaEventCreateWithFlags(&evFork, cudaEventDisableTiming);
        cudaEventCreateWithFlags(&evJoin, cudaEventDisableTiming);
        cudaFuncSetAttribute(node_kernel, cudaFuncAttributeMaxDynamicSharedMemorySize, SMEM_BYTES);
        cudaFuncSetAttribute(post_kernel, cudaFuncAttributeMaxDynamicSharedMemorySize, SMEM_BYTES);
    }

    // fork: CSR build runs concurrently with node-phase GEMMs
    cudaEventRecord(evFork, 0);
    cudaStreamWaitEvent(sB, evFork, 0);
    zero_counts_kernel<<<(NN + 255)/256, 256, 0, sB>>>();
    hist_kernel<<<(EE + 255)/256, 256, 0, sB>>>(dst);
    scan_kernel<<<1, 1024, 0, sB>>>();
    scatter_kernel<<<(EE + 255)/256, 256, 0, sB>>>(src, dst);
    cudaEventRecord(evJoin, sB);

    precompute_kernel<<<128, 128>>>(Wq, bq, Wk, bk);
    node_kernel<<<ROWS/TM, 256, SMEM_BYTES>>>(x, Wp);

    cudaStreamWaitEvent(0, evJoin, 0);
    agg_kernel<<<ROWS/8, 256>>>();
    post_kernel<<<ROWS/TM, 256, SMEM_BYTES>>>(Wv, bv, lng, lnb, out);
}

// round 12
// speedup vs baseline: 1.0085x; 1.0085x over previous
#include <cuda_runtime.h>
#include <cuda_fp16.h>
#include <math.h>

#define BB 2
#define NN 20000
#define EE 320000
#define DD 128
#define ROWS (BB*NN)          // 40000, divisible by TM
#define TM 64
#define APITCH 68
#define BPITCH 132
#define SMEM_BYTES ((128*APITCH + 128*BPITCH)*4)   // 102400 bytes -> 2 CTAs/SM

// ---- scratch (device globals; no allocation allowed) ----
__device__ __half2 g_hh[ROWS*64];   // h in fp16 (row-major, 64 half2 per row)  10 MB
__device__ float g_w[ROWS];         // exp(alpha) per node
__device__ float g_P[ROWS*DD];      // softmax-weighted mean of h  (per dst)
__device__ float g_S[ROWS*DD];      // plain mean of h             (per dst)
__device__ float g_M[DD*DD];        // Wq @ Wk^T
__device__ float g_u[DD];           // Wq bk + Wk bq
__device__ float g_c;               // bq . bk
__device__ int   g_counts[NN];
__device__ int   g_offsets[NN+1];
__device__ int   g_cursor[NN];
__device__ int   g_srcsorted[EE];   // src ids grouped by dst (CSR)

// ======================= precompute: M = Wq Wk^T, u, c =======================
// alpha_i = 0.25 * ( h_i M h_i^T + h_i . u + c )

__global__ __launch_bounds__(128)
void precompute_kernel(const float* __restrict__ Wq, const float* __restrict__ bq,
                       const float* __restrict__ Wk, const float* __restrict__ bk) {
    __shared__ float wq_row[128];
    __shared__ float red[128];
    const int k = blockIdx.x;
    const int l = threadIdx.x;

    wq_row[l] = Wq[k*128 + l];
    __syncthreads();

    const float* __restrict__ wkr = Wk + l*128;
    float acc = 0.f;
#pragma unroll 8
    for (int j = 0; j < 128; ++j)
        acc += wq_row[j] * __ldg(wkr + j);
    g_M[k*128 + l] = acc;   // M[k][l] = dot(Wq row k, Wk row l)

    red[l] = wq_row[l] * bk[l] + Wk[k*128 + l] * bq[l];
    __syncthreads();
    for (int off = 64; off; off >>= 1) {
        if (l < off) red[l] += red[l + off];
        __syncthreads();
    }
    if (l == 0) g_u[k] = red[0];

    if (k == 0) {
        __syncthreads();
        red[l] = bq[l] * bk[l];
        __syncthreads();
        for (int off = 64; off; off >>= 1) {
            if (l < off) red[l] += red[l + off];
            __syncthreads();
        }
        if (l == 0) g_c = red[0];
    }
}

// ======================= shared GEMM pieces =======================

__device__ __forceinline__ void gemm64(const float* __restrict__ A,
                                       const float* __restrict__ Bs,
                                       float acc[4][8], int ty4, int tx8) {
#pragma unroll 4
    for (int kk = 0; kk < 128; ++kk) {
        const float4 a0 = *reinterpret_cast<const float4*>(A + kk*APITCH + ty4);
        const float4 b0 = *reinterpret_cast<const float4*>(Bs + kk*BPITCH + tx8);
        const float4 b1 = *reinterpret_cast<const float4*>(Bs + kk*BPITCH + tx8 + 4);
        float av[4] = {a0.x, a0.y, a0.z, a0.w};
        float bw[8] = {b0.x, b0.y, b0.z, b0.w, b1.x, b1.y, b1.z, b1.w};
#pragma unroll
        for (int r = 0; r < 4; ++r)
#pragma unroll
            for (int c = 0; c < 8; ++c)
                acc[r][c] += av[r] * bw[c];
    }
}

__device__ __forceinline__ void load_w(const float* __restrict__ W, float* Bs, int tid) {
    for (int idx = tid; idx < DD*DD; idx += 256)
        Bs[(idx >> 7)*BPITCH + (idx & 127)] = W[idx];
}

// ======================= node phase: h, alpha -> fp16 h + exp(alpha) ==========

__global__ __launch_bounds__(256, 2)
void node_kernel(const float* __restrict__ x, const float* __restrict__ Wp) {
    extern __shared__ float sm[];
    float* A  = sm;                 // 128(k) x APITCH : x^T then h^T
    float* Bs = sm + 128*APITCH;    // 128 x BPITCH   : weight matrix
    __shared__ float alpha_sh[TM];

    const int tid = threadIdx.x;
    const int tx  = tid & 15, ty = tid >> 4;
    const int tx8 = tx * 8,  ty4 = ty * 4;
    const int row0 = blockIdx.x * TM;      // ROWS % TM == 0 -> no bounds checks

    if (tid < TM) alpha_sh[tid] = g_c;

    // load x^T and Wp
    for (int idx = tid; idx < TM*DD; idx += 256) {
        int m = idx >> 7, k = idx & 127;
        A[k*APITCH + m] = x[(size_t)(row0 + m)*DD + k];
    }
    load_w(Wp, Bs, tid);
    __syncthreads();

    float acc[4][8];
#pragma unroll
    for (int r = 0; r < 4; ++r)
#pragma unroll
        for (int c = 0; c < 8; ++c) acc[r][c] = 0.f;
    gemm64(A, Bs, acc, ty4, tx8);          // acc = h tile
    __syncthreads();

    // keep h in registers, store h^T into A; stage M
    float hreg[4][8];
#pragma unroll
    for (int r = 0; r < 4; ++r)
#pragma unroll
        for (int c = 0; c < 8; ++c) {
            hreg[r][c] = acc[r][c];
            A[(tx8 + c)*APITCH + ty4 + r] = acc[r][c];
        }
    load_w(g_M, Bs, tid);
    __syncthreads();

    // store h as fp16 (row-major half2), straight from registers
#pragma unroll
    for (int r = 0; r < 4; ++r) {
        size_t base = (size_t)(row0 + ty4 + r) * 64 + tx * 4;
#pragma unroll
        for (int j = 0; j < 4; ++j)
            g_hh[base + j] = __floats2half2_rn(hreg[r][2*j], hreg[r][2*j + 1]);
    }

    // t = h @ M ; alpha += (t + u) . h
#pragma unroll
    for (int r = 0; r < 4; ++r)
#pragma unroll
        for (int c = 0; c < 8; ++c) acc[r][c] = 0.f;
    gemm64(A, Bs, acc, ty4, tx8);
    {
        float4 u0 = *reinterpret_cast<const float4*>(g_u + tx8);
        float4 u1 = *reinterpret_cast<const float4*>(g_u + tx8 + 4);
        float ub[8] = {u0.x,u0.y,u0.z,u0.w,u1.x,u1.y,u1.z,u1.w};
#pragma unroll
        for (int r = 0; r < 4; ++r) {
            float p = 0.f;
#pragma unroll
            for (int c = 0; c < 8; ++c) p += (acc[r][c] + ub[c]) * hreg[r][c];
            atomicAdd(&alpha_sh[ty4 + r], p);
        }
    }
    __syncthreads();
    if (tid < TM)
        g_w[row0 + tid] = __expf(alpha_sh[tid] * 0.25f);   // scale = 1/sqrt(16)
}

// ======================= CSR build =======================

__global__ void zero_counts_kernel() {
    int i = blockIdx.x * blockDim.x + threadIdx.x;
    if (i < NN) g_counts[i] = 0;
}

__global__ void hist_kernel(const int* __restrict__ dst) {
    int e = blockIdx.x * blockDim.x + threadIdx.x;
    if (e < EE) atomicAdd(&g_counts[dst[e]], 1);
}

__global__ __launch_bounds__(1024)
void scan_kernel() {
    __shared__ int wsum[32];
    const int tid = threadIdx.x, lane = tid & 31, wid = tid >> 5;
    const int C = 20;
    const int base = tid * C;
    int loc[C];
    int s = 0;
#pragma unroll
    for (int i = 0; i < C; ++i) {
        int idx = base + i;
        int v = (idx < NN) ? g_counts[idx] : 0;
        loc[i] = s; s += v;
    }
    int inc = s;
#pragma unroll
    for (int off = 1; off < 32; off <<= 1) {
        int t = __shfl_up_sync(0xffffffffu, inc, off);
        if (lane >= off) inc += t;
    }
    if (lane == 31) wsum[wid] = inc;
    __syncthreads();
    if (wid == 0) {
        int w = wsum[lane];
#pragma unroll
        for (int off = 1; off < 32; off <<= 1) {
            int t = __shfl_up_sync(0xffffffffu, w, off);
            if (lane >= off) w += t;
        }
        wsum[lane] = w;
    }
    __syncthreads();
    int excl = (wid ? wsum[wid-1] : 0) + inc - s;
#pragma unroll
    for (int i = 0; i < C; ++i) {
        int idx = base + i;
        if (idx < NN) { int e = excl + loc[i]; g_offsets[idx] = e; g_cursor[idx] = e; }
    }
    if (tid == 0) g_offsets[NN] = wsum[31];
}

__global__ void scatter_kernel(const int* __restrict__ src, const int* __restrict__ dst) {
    int e = blockIdx.x * blockDim.x + threadIdx.x;
    if (e < EE) {
        int d = dst[e];
        int pos = atomicAdd(&g_cursor[d], 1);
        g_srcsorted[pos] = src[e];
    }
}

// ========== per-dst aggregation: P = softmax-weighted mean(h), S = mean(h) =====

__global__ __launch_bounds__(256)
void agg_kernel() {
    const int gw   = blockIdx.x * 8 + (threadIdx.x >> 5);   // (b, node)
    const int lane = threadIdx.x & 31;
    if (gw >= ROWS) return;
    const int b = (gw >= NN) ? 1 : 0;
    const int n = gw - b * NN;

    const int off = g_offsets[n];
    const int cnt = g_offsets[n + 1] - off;
    const float* __restrict__ w_b = g_w + b * NN;
    const uint2* __restrict__ hp  = reinterpret_cast<const uint2*>(g_hh) + (size_t)b * NN * 32;

    float a0=0.f,a1=0.f,a2=0.f,a3=0.f;      // weighted accumulation
    float h0=0.f,h1=0.f,h2=0.f,h3=0.f;      // plain accumulation
    float wsum_l = 0.f;

    for (int c0 = 0; c0 < cnt; c0 += 32) {
        int rem = cnt - c0; if (rem > 32) rem = 32;
        int   s_l = 0;
        float w_l = 0.f;
        if (lane < rem) {
            s_l = g_srcsorted[off + c0 + lane];
            w_l = w_b[s_l];
        }
        wsum_l += w_l;
#pragma unroll 4
        for (int jj = 0; jj < rem; ++jj) {
            int   s = __shfl_sync(0xffffffffu, s_l, jj);
            float w = __shfl_sync(0xffffffffu, w_l, jj);
            // lane owns dims 4*lane .. 4*lane+3 : one uint2 = 4 halves
            uint2 raw = hp[(size_t)s * 32 + lane];
            float2 f01 = __half22float2(*reinterpret_cast<const __half2*>(&raw.x));
            float2 f23 = __half22float2(*reinterpret_cast<const __half2*>(&raw.y));
            a0 += w*f01.x; a1 += w*f01.y; a2 += w*f23.x; a3 += w*f23.y;
            h0 += f01.x;   h1 += f01.y;   h2 += f23.x;   h3 += f23.y;
        }
    }

    float ssum = wsum_l;
#pragma unroll
    for (int o = 16; o; o >>= 1) ssum += __shfl_xor_sync(0xffffffffu, ssum, o);

    const float invs = (cnt > 0) ? (1.f / ssum) : 0.f;
    const float invc = 1.f / fmaxf((float)cnt, 1.f);

    float4 P; P.x = a0*invs; P.y = a1*invs; P.z = a2*invs; P.w = a3*invs;
    float4 S; S.x = h0*invc; S.y = h1*invc; S.z = h2*invc; S.w = h3*invc;
    *reinterpret_cast<float4*>(g_P + (size_t)gw*DD + lane*4) = P;
    *reinterpret_cast<float4*>(g_S + (size_t)gw*DD + lane*4) = S;
}

// ========== post: out = LN( P@Wv + bv + S ) =====================================

__global__ __launch_bounds__(256, 2)
void post_kernel(const float* __restrict__ Wv, const float* __restrict__ bv,
                 const float* __restrict__ lng, const float* __restrict__ lnb,
                 float* __restrict__ out) {
    extern __shared__ float sm[];
    float* A  = sm;                 // P^T tile
    float* Bs = sm + 128*APITCH;    // Wv
    __shared__ float sh_sum[TM];
    __shared__ float sh_sq[TM];

    const int tid = threadIdx.x;
    const int tx  = tid & 15, ty = tid >> 4;
    const int tx8 = tx * 8,  ty4 = ty * 4;
    const int row0 = blockIdx.x * TM;

    if (tid < TM) { sh_sum[tid] = 0.f; sh_sq[tid] = 0.f; }

    for (int idx = tid; idx < TM*DD; idx += 256) {
        int m = idx >> 7, k = idx & 127;
        A[k*APITCH + m] = g_P[(size_t)(row0 + m)*DD + k];
    }
    load_w(Wv, Bs, tid);
    __syncthreads();

    float acc[4][8];
#pragma unroll
    for (int r = 0; r < 4; ++r)
#pragma unroll
        for (int c = 0; c < 8; ++c) acc[r][c] = 0.f;
    gemm64(A, Bs, acc, ty4, tx8);

    // epilogue: + bv + S, cnt==0 guard, LN partials
    float4 b0 = *reinterpret_cast<const float4*>(bv + tx8);
    float4 b1 = *reinterpret_cast<const float4*>(bv + tx8 + 4);
    float bb[8] = {b0.x,b0.y,b0.z,b0.w,b1.x,b1.y,b1.z,b1.w};

#pragma unroll
    for (int r = 0; r < 4; ++r) {
        const int row = row0 + ty4 + r;
        const int n   = (row >= NN) ? row - NN : row;
        const int cnt = g_offsets[n + 1] - g_offsets[n];
        float4 s0 = *reinterpret_cast<const float4*>(g_S + (size_t)row*DD + tx8);
        float4 s1 = *reinterpret_cast<const float4*>(g_S + (size_t)row*DD + tx8 + 4);
        float ss[8] = {s0.x,s0.y,s0.z,s0.w,s1.x,s1.y,s1.z,s1.w};
        float psum = 0.f, psq = 0.f;
#pragma unroll
        for (int c = 0; c < 8; ++c) {
            float v = (cnt > 0) ? (acc[r][c] + bb[c] + ss[c]) : 0.f;
            acc[r][c] = v;
            psum += v;
            psq  += v * v;
        }
        atomicAdd(&sh_sum[ty4 + r], psum);
        atomicAdd(&sh_sq [ty4 + r], psq);
    }
    __syncthreads();

    float4 g0 = *reinterpret_cast<const float4*>(lng + tx8);
    float4 g1 = *reinterpret_cast<const float4*>(lng + tx8 + 4);
    float4 e0 = *reinterpret_cast<const float4*>(lnb + tx8);
    float4 e1 = *reinterpret_cast<const float4*>(lnb + tx8 + 4);
    float gg[8] = {g0.x,g0.y,g0.z,g0.w,g1.x,g1.y,g1.z,g1.w};
    float eb[8] = {e0.x,e0.y,e0.z,e0.w,e1.x,e1.y,e1.z,e1.w};

#pragma unroll
    for (int r = 0; r < 4; ++r) {
        const int row = row0 + ty4 + r;
        const float mean = sh_sum[ty4 + r] * (1.f/128.f);
        const float var  = sh_sq [ty4 + r] * (1.f/128.f) - mean*mean;
        const float rs   = rsqrtf(var + 1e-5f);
        float res[8];
#pragma unroll
        for (int c = 0; c < 8; ++c)
            res[c] = (acc[r][c] - mean) * rs * gg[c] + eb[c];
        float4 w0 = {res[0],res[1],res[2],res[3]};
        float4 w1 = {res[4],res[5],res[6],res[7]};
        *reinterpret_cast<float4*>(out + (size_t)row*DD + tx8)     = w0;
        *reinterpret_cast<float4*>(out + (size_t)row*DD + tx8 + 4) = w1;
    }
}

// ======================= launch =======================

extern "C" void kernel_launch(void* const* d_in, const int* in_sizes, int n_in,
                              void* d_out, int out_size) {
    const float* x    = (const float*)d_in[0];
    const float* Wp   = (const float*)d_in[1];
    const float* Wq   = (const float*)d_in[2];
    const float* bq   = (const float*)d_in[3];
    const float* Wk   = (const float*)d_in[4];
    const float* bk   = (const float*)d_in[5];
    const float* Wv   = (const float*)d_in[6];
    const float* bv   = (const float*)d_in[7];
    const float* lng  = (const float*)d_in[8];
    const float* lnb  = (const float*)d_in[9];
    const int*   ei   = (const int*)d_in[10];
    const int*   src  = ei;
    const int*   dst  = ei + EE;
    float* out = (float*)d_out;

    static cudaStream_t sB = nullptr;
    static cudaEvent_t evFork = nullptr, evJoin = nullptr;
    if (!sB) {
        cudaStreamCreateWithFlags(&sB, cudaStreamNonBlocking);
        cudaEventCreateWithFlags(&evFork, cudaEventDisableTiming);
        cudaEventCreateWithFlags(&evJoin, cudaEventDisableTiming);
        cudaFuncSetAttribute(node_kernel, cudaFuncAttributeMaxDynamicSharedMemorySize, SMEM_BYTES);
        cudaFuncSetAttribute(post_kernel, cudaFuncAttributeMaxDynamicSharedMemorySize, SMEM_BYTES);
    }

    // fork: CSR build runs concurrently with node-phase GEMMs
    cudaEventRecord(evFork, 0);
    cudaStreamWaitEvent(sB, evFork, 0);
    zero_counts_kernel<<<(NN + 255)/256, 256, 0, sB>>>();
    hist_kernel<<<(EE + 255)/256, 256, 0, sB>>>(dst);
    scan_kernel<<<1, 1024, 0, sB>>>();
    scatter_kernel<<<(EE + 255)/256, 256, 0, sB>>>(src, dst);
    cudaEventRecord(evJoin, sB);

    precompute_kernel<<<128, 128>>>(Wq, bq, Wk, bk);
    node_kernel<<<ROWS/TM, 256, SMEM_BYTES>>>(x, Wp);

    cudaStreamWaitEvent(0, evJoin, 0);
    agg_kernel<<<ROWS/8, 256>>>();
    post_kernel<<<ROWS/TM, 256, SMEM_BYTES>>>(Wv, bv, lng, lnb, out);
}

// round 13
// speedup vs baseline: 1.0204x; 1.0118x over previous
#include <cuda_runtime.h>
#include <cuda_fp16.h>
#include <math.h>

#define BB 2
#define NN 20000
#define EE 320000
#define DD 128
#define ROWS (BB*NN)          // 40000, divisible by TM
#define TM 64
#define APITCH 68
#define BPITCH 132
#define SMEM_BYTES ((128*APITCH + 128*BPITCH)*4)   // 102400 bytes -> 2 CTAs/SM

// ---- scratch (device globals; no allocation allowed) ----
__device__ __half2 g_hh[ROWS*64];   // h in fp16 (row-major, 64 half2 per row)  10 MB
__device__ float g_w[ROWS];         // exp(alpha) per node
__device__ float g_P[ROWS*DD];      // softmax-weighted mean of h  (per dst)
__device__ float g_S[ROWS*DD];      // plain mean of h             (per dst)
__device__ float g_M[DD*DD];        // Wq @ Wk^T
__device__ float g_u[DD];           // Wq bk + Wk bq
__device__ float g_c;               // bq . bk
__device__ int   g_counts[NN];
__device__ int   g_offsets[NN+1];
__device__ int   g_cursor[NN];
__device__ int   g_srcsorted[EE];   // src ids grouped by dst (CSR)

// ======================= precompute: M = Wq Wk^T, u, c =======================
// alpha_i = 0.25 * ( h_i M h_i^T + h_i . u + c )

__global__ __launch_bounds__(128)
void precompute_kernel(const float* __restrict__ Wq, const float* __restrict__ bq,
                       const float* __restrict__ Wk, const float* __restrict__ bk) {
    __shared__ float wq_row[128];
    __shared__ float red[128];
    const int k = blockIdx.x;
    const int l = threadIdx.x;

    wq_row[l] = Wq[k*128 + l];
    __syncthreads();

    const float* __restrict__ wkr = Wk + l*128;
    float acc = 0.f;
#pragma unroll 8
    for (int j = 0; j < 128; ++j)
        acc += wq_row[j] * __ldg(wkr + j);
    g_M[k*128 + l] = acc;   // M[k][l] = dot(Wq row k, Wk row l)

    red[l] = wq_row[l] * bk[l] + Wk[k*128 + l] * bq[l];
    __syncthreads();
    for (int off = 64; off; off >>= 1) {
        if (l < off) red[l] += red[l + off];
        __syncthreads();
    }
    if (l == 0) g_u[k] = red[0];

    if (k == 0) {
        __syncthreads();
        red[l] = bq[l] * bk[l];
        __syncthreads();
        for (int off = 64; off; off >>= 1) {
            if (l < off) red[l] += red[l + off];
            __syncthreads();
        }
        if (l == 0) g_c = red[0];
    }
}

// ======================= shared GEMM pieces =======================

__device__ __forceinline__ void gemm64(const float* __restrict__ A,
                                       const float* __restrict__ Bs,
                                       float acc[4][8], int ty4, int tx8) {
#pragma unroll 4
    for (int kk = 0; kk < 128; ++kk) {
        const float4 a0 = *reinterpret_cast<const float4*>(A + kk*APITCH + ty4);
        const float4 b0 = *reinterpret_cast<const float4*>(Bs + kk*BPITCH + tx8);
        const float4 b1 = *reinterpret_cast<const float4*>(Bs + kk*BPITCH + tx8 + 4);
        float av[4] = {a0.x, a0.y, a0.z, a0.w};
        float bw[8] = {b0.x, b0.y, b0.z, b0.w, b1.x, b1.y, b1.z, b1.w};
#pragma unroll
        for (int r = 0; r < 4; ++r)
#pragma unroll
            for (int c = 0; c < 8; ++c)
                acc[r][c] += av[r] * bw[c];
    }
}

__device__ __forceinline__ void load_w(const float* __restrict__ W, float* Bs, int tid) {
    for (int idx = tid; idx < DD*DD; idx += 256)
        Bs[(idx >> 7)*BPITCH + (idx & 127)] = W[idx];
}

// ======================= node phase: h, alpha -> fp16 h + exp(alpha) ==========

__global__ __launch_bounds__(256, 2)
void node_kernel(const float* __restrict__ x, const float* __restrict__ Wp) {
    extern __shared__ float sm[];
    float* A  = sm;                 // 128(k) x APITCH : x^T then h^T
    float* Bs = sm + 128*APITCH;    // 128 x BPITCH   : weight matrix
    __shared__ float alpha_sh[TM];

    const int tid = threadIdx.x;
    const int tx  = tid & 15, ty = tid >> 4;
    const int tx8 = tx * 8,  ty4 = ty * 4;
    const int row0 = blockIdx.x * TM;      // ROWS % TM == 0 -> no bounds checks

    if (tid < TM) alpha_sh[tid] = g_c;

    // load x^T and Wp
    for (int idx = tid; idx < TM*DD; idx += 256) {
        int m = idx >> 7, k = idx & 127;
        A[k*APITCH + m] = x[(size_t)(row0 + m)*DD + k];
    }
    load_w(Wp, Bs, tid);
    __syncthreads();

    float acc[4][8];
#pragma unroll
    for (int r = 0; r < 4; ++r)
#pragma unroll
        for (int c = 0; c < 8; ++c) acc[r][c] = 0.f;
    gemm64(A, Bs, acc, ty4, tx8);          // acc = h tile
    __syncthreads();

    // keep h in registers, store h^T into A; stage M
    float hreg[4][8];
#pragma unroll
    for (int r = 0; r < 4; ++r)
#pragma unroll
        for (int c = 0; c < 8; ++c) {
            hreg[r][c] = acc[r][c];
            A[(tx8 + c)*APITCH + ty4 + r] = acc[r][c];
        }
    load_w(g_M, Bs, tid);
    __syncthreads();

    // store h as fp16 (row-major half2), straight from registers
#pragma unroll
    for (int r = 0; r < 4; ++r) {
        size_t base = (size_t)(row0 + ty4 + r) * 64 + tx * 4;
#pragma unroll
        for (int j = 0; j < 4; ++j)
            g_hh[base + j] = __floats2half2_rn(hreg[r][2*j], hreg[r][2*j + 1]);
    }

    // t = h @ M ; alpha += (t + u) . h
#pragma unroll
    for (int r = 0; r < 4; ++r)
#pragma unroll
        for (int c = 0; c < 8; ++c) acc[r][c] = 0.f;
    gemm64(A, Bs, acc, ty4, tx8);
    {
        float4 u0 = *reinterpret_cast<const float4*>(g_u + tx8);
        float4 u1 = *reinterpret_cast<const float4*>(g_u + tx8 + 4);
        float ub[8] = {u0.x,u0.y,u0.z,u0.w,u1.x,u1.y,u1.z,u1.w};
#pragma unroll
        for (int r = 0; r < 4; ++r) {
            float p = 0.f;
#pragma unroll
            for (int c = 0; c < 8; ++c) p += (acc[r][c] + ub[c]) * hreg[r][c];
            atomicAdd(&alpha_sh[ty4 + r], p);
        }
    }
    __syncthreads();
    if (tid < TM)
        g_w[row0 + tid] = __expf(alpha_sh[tid] * 0.25f);   // scale = 1/sqrt(16)
}

// ======================= CSR build =======================

__global__ void zero_counts_kernel() {
    int i = blockIdx.x * blockDim.x + threadIdx.x;
    if (i < NN) g_counts[i] = 0;
}

__global__ void hist_kernel(const int* __restrict__ dst) {
    int e = blockIdx.x * blockDim.x + threadIdx.x;
    if (e < EE) atomicAdd(&g_counts[dst[e]], 1);
}

__global__ __launch_bounds__(1024)
void scan_kernel() {
    __shared__ int wsum[32];
    const int tid = threadIdx.x, lane = tid & 31, wid = tid >> 5;
    const int C = 20;
    const int base = tid * C;
    int loc[C];
    int s = 0;
#pragma unroll
    for (int i = 0; i < C; ++i) {
        int idx = base + i;
        int v = (idx < NN) ? g_counts[idx] : 0;
        loc[i] = s; s += v;
    }
    int inc = s;
#pragma unroll
    for (int off = 1; off < 32; off <<= 1) {
        int t = __shfl_up_sync(0xffffffffu, inc, off);
        if (lane >= off) inc += t;
    }
    if (lane == 31) wsum[wid] = inc;
    __syncthreads();
    if (wid == 0) {
        int w = wsum[lane];
#pragma unroll
        for (int off = 1; off < 32; off <<= 1) {
            int t = __shfl_up_sync(0xffffffffu, w, off);
            if (lane >= off) w += t;
        }
        wsum[lane] = w;
    }
    __syncthreads();
    int excl = (wid ? wsum[wid-1] : 0) + inc - s;
#pragma unroll
    for (int i = 0; i < C; ++i) {
        int idx = base + i;
        if (idx < NN) { int e = excl + loc[i]; g_offsets[idx] = e; g_cursor[idx] = e; }
    }
    if (tid == 0) g_offsets[NN] = wsum[31];
}

__global__ void scatter_kernel(const int* __restrict__ src, const int* __restrict__ dst) {
    int e = blockIdx.x * blockDim.x + threadIdx.x;
    if (e < EE) {
        int d = dst[e];
        int pos = atomicAdd(&g_cursor[d], 1);
        g_srcsorted[pos] = src[e];
    }
}

// ========== per-dst aggregation: P = softmax-weighted mean(h), S = mean(h) =====

__global__ __launch_bounds__(256)
void agg_kernel() {
    const int gw   = blockIdx.x * 8 + (threadIdx.x >> 5);   // (b, node)
    const int lane = threadIdx.x & 31;
    if (gw >= ROWS) return;
    const int b = (gw >= NN) ? 1 : 0;
    const int n = gw - b * NN;

    const int off = g_offsets[n];
    const int cnt = g_offsets[n + 1] - off;
    const float* __restrict__ w_b = g_w + b * NN;
    const uint2* __restrict__ hp  = reinterpret_cast<const uint2*>(g_hh) + (size_t)b * NN * 32;

    float a0=0.f,a1=0.f,a2=0.f,a3=0.f;      // weighted accumulation
    float h0=0.f,h1=0.f,h2=0.f,h3=0.f;      // plain accumulation
    float wsum_l = 0.f;

    for (int c0 = 0; c0 < cnt; c0 += 32) {
        int rem = cnt - c0; if (rem > 32) rem = 32;
        int   s_l = 0;
        float w_l = 0.f;
        if (lane < rem) {
            s_l = g_srcsorted[off + c0 + lane];
            w_l = w_b[s_l];
        }
        wsum_l += w_l;
#pragma unroll 4
        for (int jj = 0; jj < rem; ++jj) {
            int   s = __shfl_sync(0xffffffffu, s_l, jj);
            float w = __shfl_sync(0xffffffffu, w_l, jj);
            // lane owns dims 4*lane .. 4*lane+3 : one uint2 = 4 halves
            uint2 raw = hp[(size_t)s * 32 + lane];
            float2 f01 = __half22float2(*reinterpret_cast<const __half2*>(&raw.x));
            float2 f23 = __half22float2(*reinterpret_cast<const __half2*>(&raw.y));
            a0 += w*f01.x; a1 += w*f01.y; a2 += w*f23.x; a3 += w*f23.y;
            h0 += f01.x;   h1 += f01.y;   h2 += f23.x;   h3 += f23.y;
        }
    }

    float ssum = wsum_l;
#pragma unroll
    for (int o = 16; o; o >>= 1) ssum += __shfl_xor_sync(0xffffffffu, ssum, o);

    const float invs = (cnt > 0) ? (1.f / ssum) : 0.f;
    const float invc = 1.f / fmaxf((float)cnt, 1.f);

    float4 P; P.x = a0*invs; P.y = a1*invs; P.z = a2*invs; P.w = a3*invs;
    float4 S; S.x = h0*invc; S.y = h1*invc; S.z = h2*invc; S.w = h3*invc;
    *reinterpret_cast<float4*>(g_P + (size_t)gw*DD + lane*4) = P;
    *reinterpret_cast<float4*>(g_S + (size_t)gw*DD + lane*4) = S;
}

// ========== post: out = LN( P@Wv + bv + S ) =====================================

__global__ __launch_bounds__(256, 2)
void post_kernel(const float* __restrict__ Wv, const float* __restrict__ bv,
                 const float* __restrict__ lng, const float* __restrict__ lnb,
                 float* __restrict__ out) {
    extern __shared__ float sm[];
    float* A  = sm;                 // P^T tile
    float* Bs = sm + 128*APITCH;    // Wv
    __shared__ float sh_sum[TM];
    __shared__ float sh_sq[TM];

    const int tid = threadIdx.x;
    const int tx  = tid & 15, ty = tid >> 4;
    const int tx8 = tx * 8,  ty4 = ty * 4;
    const int row0 = blockIdx.x * TM;

    if (tid < TM) { sh_sum[tid] = 0.f; sh_sq[tid] = 0.f; }

    for (int idx = tid; idx < TM*DD; idx += 256) {
        int m = idx >> 7, k = idx & 127;
        A[k*APITCH + m] = g_P[(size_t)(row0 + m)*DD + k];
    }
    load_w(Wv, Bs, tid);
    __syncthreads();

    float acc[4][8];
#pragma unroll
    for (int r = 0; r < 4; ++r)
#pragma unroll
        for (int c = 0; c < 8; ++c) acc[r][c] = 0.f;
    gemm64(A, Bs, acc, ty4, tx8);

    // epilogue: + bv + S, cnt==0 guard, LN partials
    float4 b0 = *reinterpret_cast<const float4*>(bv + tx8);
    float4 b1 = *reinterpret_cast<const float4*>(bv + tx8 + 4);
    float bb[8] = {b0.x,b0.y,b0.z,b0.w,b1.x,b1.y,b1.z,b1.w};

#pragma unroll
    for (int r = 0; r < 4; ++r) {
        const int row = row0 + ty4 + r;
        const int n   = (row >= NN) ? row - NN : row;
        const int cnt = g_offsets[n + 1] - g_offsets[n];
        float4 s0 = *reinterpret_cast<const float4*>(g_S + (size_t)row*DD + tx8);
        float4 s1 = *reinterpret_cast<const float4*>(g_S + (size_t)row*DD + tx8 + 4);
        float ss[8] = {s0.x,s0.y,s0.z,s0.w,s1.x,s1.y,s1.z,s1.w};
        float psum = 0.f, psq = 0.f;
#pragma unroll
        for (int c = 0; c < 8; ++c) {
            float v = (cnt > 0) ? (acc[r][c] + bb[c] + ss[c]) : 0.f;
            acc[r][c] = v;
            psum += v;
            psq  += v * v;
        }
        atomicAdd(&sh_sum[ty4 + r], psum);
        atomicAdd(&sh_sq [ty4 + r], psq);
    }
    __syncthreads();

    float4 g0 = *reinterpret_cast<const float4*>(lng + tx8);
    float4 g1 = *reinterpret_cast<const float4*>(lng + tx8 + 4);
    float4 e0 = *reinterpret_cast<const float4*>(lnb + tx8);
    float4 e1 = *reinterpret_cast<const float4*>(lnb + tx8 + 4);
    float gg[8] = {g0.x,g0.y,g0.z,g0.w,g1.x,g1.y,g1.z,g1.w};
    float eb[8] = {e0.x,e0.y,e0.z,e0.w,e1.x,e1.y,e1.z,e1.w};

#pragma unroll
    for (int r = 0; r < 4; ++r) {
        const int row = row0 + ty4 + r;
        const float mean = sh_sum[ty4 + r] * (1.f/128.f);
        const float var  = sh_sq [ty4 + r] * (1.f/128.f) - mean*mean;
        const float rs   = rsqrtf(var + 1e-5f);
        float res[8];
#pragma unroll
        for (int c = 0; c < 8; ++c)
            res[c] = (acc[r][c] - mean) * rs * gg[c] + eb[c];
        float4 w0 = {res[0],res[1],res[2],res[3]};
        float4 w1 = {res[4],res[5],res[6],res[7]};
        *reinterpret_cast<float4*>(out + (size_t)row*DD + tx8)     = w0;
        *reinterpret_cast<float4*>(out + (size_t)row*DD + tx8 + 4) = w1;
    }
}

// ======================= launch =======================

extern "C" void kernel_launch(void* const* d_in, const int* in_sizes, int n_in,
                              void* d_out, int out_size) {
    const float* x    = (const float*)d_in[0];
    const float* Wp   = (const float*)d_in[1];
    const float* Wq   = (const float*)d_in[2];
    const float* bq   = (const float*)d_in[3];
    const float* Wk   = (const float*)d_in[4];
    const float* bk   = (const float*)d_in[5];
    const float* Wv   = (const float*)d_in[6];
    const float* bv   = (const float*)d_in[7];
    const float* lng  = (const float*)d_in[8];
    const float* lnb  = (const float*)d_in[9];
    const int*   ei   = (const int*)d_in[10];
    const int*   src  = ei;
    const int*   dst  = ei + EE;
    float* out = (float*)d_out;

    static cudaStream_t sB = nullptr;
    static cudaEvent_t evFork = nullptr, evJoin = nullptr;
    if (!sB) {
        cudaStreamCreateWithFlags(&sB, cudaStreamNonBlocking);
        cudaEventCreateWithFlags(&evFork, cudaEventDisableTiming);
        cudaEventCreateWithFlags(&evJoin, cudaEventDisableTiming);
        cudaFuncSetAttribute(node_kernel, cudaFuncAttributeMaxDynamicSharedMemorySize, SMEM_BYTES);
        cudaFuncSetAttribute(post_kernel, cudaFuncAttributeMaxDynamicSharedMemorySize, SMEM_BYTES);
    }

    // fork: CSR build runs concurrently with node-phase GEMMs
    cudaEventRecord(evFork, 0);
    cudaStreamWaitEvent(sB, evFork, 0);
    zero_counts_kernel<<<(NN + 255)/256, 256, 0, sB>>>();
    hist_kernel<<<(EE + 255)/256, 256, 0, sB>>>(dst);
    scan_kernel<<<1, 1024, 0, sB>>>();
    scatter_kernel<<<(EE + 255)/256, 256, 0, sB>>>(src, dst);
    cudaEventRecord(evJoin, sB);

    precompute_kernel<<<128, 128>>>(Wq, bq, Wk, bk);
    node_kernel<<<ROWS/TM, 256, SMEM_BYTES>>>(x, Wp);

    cudaStreamWaitEvent(0, evJoin, 0);
    agg_kernel<<<ROWS/8, 256>>>();
    post_kernel<<<ROWS/TM, 256, SMEM_BYTES>>>(Wv, bv, lng, lnb, out);
}

// round 14
// speedup vs baseline: 1.0369x; 1.0162x over previous
#include <cuda_runtime.h>
#include <cuda_fp16.h>
#include <math.h>

#define BB 2
#define NN 20000
#define EE 320000
#define DD 128
#define ROWS (BB*NN)          // 40000, divisible by TM
#define TM 64
#define APITCH 68
#define BPITCH 132
#define SMEM_BYTES ((128*APITCH + 128*BPITCH)*4)   // 102400 bytes -> 2 CTAs/SM

// ---- scratch (device globals; no allocation allowed) ----
__device__ __half2 g_hh[ROWS*64];   // h in fp16 (row-major, 64 half2 per row)  10 MB
__device__ float g_w[ROWS];         // exp(alpha) per node
__device__ float g_P[ROWS*DD];      // softmax-weighted mean of h  (per dst)
__device__ float g_S[ROWS*DD];      // plain mean of h             (per dst)
__device__ float g_M[DD*DD];        // Wq @ Wk^T
__device__ float g_u[DD];           // Wq bk + Wk bq
__device__ float g_c;               // bq . bk
__device__ int   g_counts[NN];
__device__ int   g_offsets[NN+1];
__device__ int   g_cursor[NN];
__device__ int   g_srcsorted[EE];   // src ids grouped by dst (CSR)

// ======================= precompute: M = Wq Wk^T, u, c =======================
// alpha_i = 0.25 * ( h_i M h_i^T + h_i . u + c )

__global__ __launch_bounds__(128)
void precompute_kernel(const float* __restrict__ Wq, const float* __restrict__ bq,
                       const float* __restrict__ Wk, const float* __restrict__ bk) {
    __shared__ float wq_row[128];
    __shared__ float red[128];
    const int k = blockIdx.x;
    const int l = threadIdx.x;

    wq_row[l] = Wq[k*128 + l];
    __syncthreads();

    const float* __restrict__ wkr = Wk + l*128;
    float acc = 0.f;
#pragma unroll 8
    for (int j = 0; j < 128; ++j)
        acc += wq_row[j] * __ldg(wkr + j);
    g_M[k*128 + l] = acc;   // M[k][l] = dot(Wq row k, Wk row l)

    red[l] = wq_row[l] * bk[l] + Wk[k*128 + l] * bq[l];
    __syncthreads();
    for (int off = 64; off; off >>= 1) {
        if (l < off) red[l] += red[l + off];
        __syncthreads();
    }
    if (l == 0) g_u[k] = red[0];

    if (k == 0) {
        __syncthreads();
        red[l] = bq[l] * bk[l];
        __syncthreads();
        for (int off = 64; off; off >>= 1) {
            if (l < off) red[l] += red[l + off];
            __syncthreads();
        }
        if (l == 0) g_c = red[0];
    }
}

// ======================= shared GEMM pieces =======================

__device__ __forceinline__ void gemm64(const float* __restrict__ A,
                                       const float* __restrict__ Bs,
                                       float acc[4][8], int ty4, int tx8) {
#pragma unroll 4
    for (int kk = 0; kk < 128; ++kk) {
        const float4 a0 = *reinterpret_cast<const float4*>(A + kk*APITCH + ty4);
        const float4 b0 = *reinterpret_cast<const float4*>(Bs + kk*BPITCH + tx8);
        const float4 b1 = *reinterpret_cast<const float4*>(Bs + kk*BPITCH + tx8 + 4);
        float av[4] = {a0.x, a0.y, a0.z, a0.w};
        float bw[8] = {b0.x, b0.y, b0.z, b0.w, b1.x, b1.y, b1.z, b1.w};
#pragma unroll
        for (int r = 0; r < 4; ++r)
#pragma unroll
            for (int c = 0; c < 8; ++c)
                acc[r][c] += av[r] * bw[c];
    }
}

__device__ __forceinline__ void load_w(const float* __restrict__ W, float* Bs, int tid) {
    for (int idx = tid; idx < DD*DD; idx += 256)
        Bs[(idx >> 7)*BPITCH + (idx & 127)] = W[idx];
}

// ======================= node phase: h, alpha -> fp16 h + exp(alpha) ==========

__global__ __launch_bounds__(256, 2)
void node_kernel(const float* __restrict__ x, const float* __restrict__ Wp) {
    extern __shared__ float sm[];
    float* A  = sm;                 // 128(k) x APITCH : x^T then h^T
    float* Bs = sm + 128*APITCH;    // 128 x BPITCH   : weight matrix
    __shared__ float alpha_sh[TM];

    const int tid = threadIdx.x;
    const int tx  = tid & 15, ty = tid >> 4;
    const int tx8 = tx * 8,  ty4 = ty * 4;
    const int row0 = blockIdx.x * TM;      // ROWS % TM == 0 -> no bounds checks

    if (tid < TM) alpha_sh[tid] = g_c;

    // load x^T and Wp
    for (int idx = tid; idx < TM*DD; idx += 256) {
        int m = idx >> 7, k = idx & 127;
        A[k*APITCH + m] = x[(size_t)(row0 + m)*DD + k];
    }
    load_w(Wp, Bs, tid);
    __syncthreads();

    float acc[4][8];
#pragma unroll
    for (int r = 0; r < 4; ++r)
#pragma unroll
        for (int c = 0; c < 8; ++c) acc[r][c] = 0.f;
    gemm64(A, Bs, acc, ty4, tx8);          // acc = h tile
    __syncthreads();

    // keep h in registers, store h^T into A; stage M
    float hreg[4][8];
#pragma unroll
    for (int r = 0; r < 4; ++r)
#pragma unroll
        for (int c = 0; c < 8; ++c) {
            hreg[r][c] = acc[r][c];
            A[(tx8 + c)*APITCH + ty4 + r] = acc[r][c];
        }
    load_w(g_M, Bs, tid);
    __syncthreads();

    // store h as fp16 (row-major half2), straight from registers
#pragma unroll
    for (int r = 0; r < 4; ++r) {
        size_t base = (size_t)(row0 + ty4 + r) * 64 + tx * 4;
#pragma unroll
        for (int j = 0; j < 4; ++j)
            g_hh[base + j] = __floats2half2_rn(hreg[r][2*j], hreg[r][2*j + 1]);
    }

    // t = h @ M ; alpha += (t + u) . h
#pragma unroll
    for (int r = 0; r < 4; ++r)
#pragma unroll
        for (int c = 0; c < 8; ++c) acc[r][c] = 0.f;
    gemm64(A, Bs, acc, ty4, tx8);
    {
        float4 u0 = *reinterpret_cast<const float4*>(g_u + tx8);
        float4 u1 = *reinterpret_cast<const float4*>(g_u + tx8 + 4);
        float ub[8] = {u0.x,u0.y,u0.z,u0.w,u1.x,u1.y,u1.z,u1.w};
#pragma unroll
        for (int r = 0; r < 4; ++r) {
            float p = 0.f;
#pragma unroll
            for (int c = 0; c < 8; ++c) p += (acc[r][c] + ub[c]) * hreg[r][c];
            atomicAdd(&alpha_sh[ty4 + r], p);
        }
    }
    __syncthreads();
    if (tid < TM)
        g_w[row0 + tid] = __expf(alpha_sh[tid] * 0.25f);   // scale = 1/sqrt(16)
}

// ======================= CSR build =======================

__global__ void zero_counts_kernel() {
    int i = blockIdx.x * blockDim.x + threadIdx.x;
    if (i < NN) g_counts[i] = 0;
}

__global__ void hist_kernel(const int* __restrict__ dst) {
    int e = blockIdx.x * blockDim.x + threadIdx.x;
    if (e < EE) atomicAdd(&g_counts[dst[e]], 1);
}

__global__ __launch_bounds__(1024)
void scan_kernel() {
    __shared__ int wsum[32];
    const int tid = threadIdx.x, lane = tid & 31, wid = tid >> 5;
    const int C = 20;
    const int base = tid * C;
    int loc[C];
    int s = 0;
#pragma unroll
    for (int i = 0; i < C; ++i) {
        int idx = base + i;
        int v = (idx < NN) ? g_counts[idx] : 0;
        loc[i] = s; s += v;
    }
    int inc = s;
#pragma unroll
    for (int off = 1; off < 32; off <<= 1) {
        int t = __shfl_up_sync(0xffffffffu, inc, off);
        if (lane >= off) inc += t;
    }
    if (lane == 31) wsum[wid] = inc;
    __syncthreads();
    if (wid == 0) {
        int w = wsum[lane];
#pragma unroll
        for (int off = 1; off < 32; off <<= 1) {
            int t = __shfl_up_sync(0xffffffffu, w, off);
            if (lane >= off) w += t;
        }
        wsum[lane] = w;
    }
    __syncthreads();
    int excl = (wid ? wsum[wid-1] : 0) + inc - s;
#pragma unroll
    for (int i = 0; i < C; ++i) {
        int idx = base + i;
        if (idx < NN) { int e = excl + loc[i]; g_offsets[idx] = e; g_cursor[idx] = e; }
    }
    if (tid == 0) g_offsets[NN] = wsum[31];
}

__global__ void scatter_kernel(const int* __restrict__ src, const int* __restrict__ dst) {
    int e = blockIdx.x * blockDim.x + threadIdx.x;
    if (e < EE) {
        int d = dst[e];
        int pos = atomicAdd(&g_cursor[d], 1);
        g_srcsorted[pos] = src[e];
    }
}

// ========== per-dst aggregation: P = softmax-weighted mean(h), S = mean(h) =====

__global__ __launch_bounds__(256)
void agg_kernel() {
    const int gw   = blockIdx.x * 8 + (threadIdx.x >> 5);   // (b, node)
    const int lane = threadIdx.x & 31;
    if (gw >= ROWS) return;
    const int b = (gw >= NN) ? 1 : 0;
    const int n = gw - b * NN;

    const int off = g_offsets[n];
    const int cnt = g_offsets[n + 1] - off;
    const float* __restrict__ w_b = g_w + b * NN;
    const uint2* __restrict__ hp  = reinterpret_cast<const uint2*>(g_hh) + (size_t)b * NN * 32;

    float a0=0.f,a1=0.f,a2=0.f,a3=0.f;      // weighted accumulation
    float h0=0.f,h1=0.f,h2=0.f,h3=0.f;      // plain accumulation
    float wsum_l = 0.f;

    for (int c0 = 0; c0 < cnt; c0 += 32) {
        int rem = cnt - c0; if (rem > 32) rem = 32;
        int   s_l = 0;
        float w_l = 0.f;
        if (lane < rem) {
            s_l = g_srcsorted[off + c0 + lane];
            w_l = w_b[s_l];
        }
        wsum_l += w_l;
#pragma unroll 4
        for (int jj = 0; jj < rem; ++jj) {
            int   s = __shfl_sync(0xffffffffu, s_l, jj);
            float w = __shfl_sync(0xffffffffu, w_l, jj);
            // lane owns dims 4*lane .. 4*lane+3 : one uint2 = 4 halves
            uint2 raw = hp[(size_t)s * 32 + lane];
            float2 f01 = __half22float2(*reinterpret_cast<const __half2*>(&raw.x));
            float2 f23 = __half22float2(*reinterpret_cast<const __half2*>(&raw.y));
            a0 += w*f01.x; a1 += w*f01.y; a2 += w*f23.x; a3 += w*f23.y;
            h0 += f01.x;   h1 += f01.y;   h2 += f23.x;   h3 += f23.y;
        }
    }

    float ssum = wsum_l;
#pragma unroll
    for (int o = 16; o; o >>= 1) ssum += __shfl_xor_sync(0xffffffffu, ssum, o);

    const float invs = (cnt > 0) ? (1.f / ssum) : 0.f;
    const float invc = 1.f / fmaxf((float)cnt, 1.f);

    float4 P; P.x = a0*invs; P.y = a1*invs; P.z = a2*invs; P.w = a3*invs;
    float4 S; S.x = h0*invc; S.y = h1*invc; S.z = h2*invc; S.w = h3*invc;
    *reinterpret_cast<float4*>(g_P + (size_t)gw*DD + lane*4) = P;
    *reinterpret_cast<float4*>(g_S + (size_t)gw*DD + lane*4) = S;
}

// ========== post: out = LN( P@Wv + bv + S ) =====================================

__global__ __launch_bounds__(256, 2)
void post_kernel(const float* __restrict__ Wv, const float* __restrict__ bv,
                 const float* __restrict__ lng, const float* __restrict__ lnb,
                 float* __restrict__ out) {
    extern __shared__ float sm[];
    float* A  = sm;                 // P^T tile
    float* Bs = sm + 128*APITCH;    // Wv
    __shared__ float sh_sum[TM];
    __shared__ float sh_sq[TM];

    const int tid = threadIdx.x;
    const int tx  = tid & 15, ty = tid >> 4;
    const int tx8 = tx * 8,  ty4 = ty * 4;
    const int row0 = blockIdx.x * TM;

    if (tid < TM) { sh_sum[tid] = 0.f; sh_sq[tid] = 0.f; }

    for (int idx = tid; idx < TM*DD; idx += 256) {
        int m = idx >> 7, k = idx & 127;
        A[k*APITCH + m] = g_P[(size_t)(row0 + m)*DD + k];
    }
    load_w(Wv, Bs, tid);
    __syncthreads();

    float acc[4][8];
#pragma unroll
    for (int r = 0; r < 4; ++r)
#pragma unroll
        for (int c = 0; c < 8; ++c) acc[r][c] = 0.f;
    gemm64(A, Bs, acc, ty4, tx8);

    // epilogue: + bv + S, cnt==0 guard, LN partials
    float4 b0 = *reinterpret_cast<const float4*>(bv + tx8);
    float4 b1 = *reinterpret_cast<const float4*>(bv + tx8 + 4);
    float bb[8] = {b0.x,b0.y,b0.z,b0.w,b1.x,b1.y,b1.z,b1.w};

#pragma unroll
    for (int r = 0; r < 4; ++r) {
        const int row = row0 + ty4 + r;
        const int n   = (row >= NN) ? row - NN : row;
        const int cnt = g_offsets[n + 1] - g_offsets[n];
        float4 s0 = *reinterpret_cast<const float4*>(g_S + (size_t)row*DD + tx8);
        float4 s1 = *reinterpret_cast<const float4*>(g_S + (size_t)row*DD + tx8 + 4);
        float ss[8] = {s0.x,s0.y,s0.z,s0.w,s1.x,s1.y,s1.z,s1.w};
        float psum = 0.f, psq = 0.f;
#pragma unroll
        for (int c = 0; c < 8; ++c) {
            float v = (cnt > 0) ? (acc[r][c] + bb[c] + ss[c]) : 0.f;
            acc[r][c] = v;
            psum += v;
            psq  += v * v;
        }
        atomicAdd(&sh_sum[ty4 + r], psum);
        atomicAdd(&sh_sq [ty4 + r], psq);
    }
    __syncthreads();

    float4 g0 = *reinterpret_cast<const float4*>(lng + tx8);
    float4 g1 = *reinterpret_cast<const float4*>(lng + tx8 + 4);
    float4 e0 = *reinterpret_cast<const float4*>(lnb + tx8);
    float4 e1 = *reinterpret_cast<const float4*>(lnb + tx8 + 4);
    float gg[8] = {g0.x,g0.y,g0.z,g0.w,g1.x,g1.y,g1.z,g1.w};
    float eb[8] = {e0.x,e0.y,e0.z,e0.w,e1.x,e1.y,e1.z,e1.w};

#pragma unroll
    for (int r = 0; r < 4; ++r) {
        const int row = row0 + ty4 + r;
        const float mean = sh_sum[ty4 + r] * (1.f/128.f);
        const float var  = sh_sq [ty4 + r] * (1.f/128.f) - mean*mean;
        const float rs   = rsqrtf(var + 1e-5f);
        float res[8];
#pragma unroll
        for (int c = 0; c < 8; ++c)
            res[c] = (acc[r][c] - mean) * rs * gg[c] + eb[c];
        float4 w0 = {res[0],res[1],res[2],res[3]};
        float4 w1 = {res[4],res[5],res[6],res[7]};
        *reinterpret_cast<float4*>(out + (size_t)row*DD + tx8)     = w0;
        *reinterpret_cast<float4*>(out + (size_t)row*DD + tx8 + 4) = w1;
    }
}

// ======================= launch =======================

extern "C" void kernel_launch(void* const* d_in, const int* in_sizes, int n_in,
                              void* d_out, int out_size) {
    const float* x    = (const float*)d_in[0];
    const float* Wp   = (const float*)d_in[1];
    const float* Wq   = (const float*)d_in[2];
    const float* bq   = (const float*)d_in[3];
    const float* Wk   = (const float*)d_in[4];
    const float* bk   = (const float*)d_in[5];
    const float* Wv   = (const float*)d_in[6];
    const float* bv   = (const float*)d_in[7];
    const float* lng  = (const float*)d_in[8];
    const float* lnb  = (const float*)d_in[9];
    const int*   ei   = (const int*)d_in[10];
    const int*   src  = ei;
    const int*   dst  = ei + EE;
    float* out = (float*)d_out;

    static cudaStream_t sB = nullptr;
    static cudaEvent_t evFork = nullptr, evJoin = nullptr;
    if (!sB) {
        cudaStreamCreateWithFlags(&sB, cudaStreamNonBlocking);
        cudaEventCreateWithFlags(&evFork, cudaEventDisableTiming);
        cudaEventCreateWithFlags(&evJoin, cudaEventDisableTiming);
        cudaFuncSetAttribute(node_kernel, cudaFuncAttributeMaxDynamicSharedMemorySize, SMEM_BYTES);
        cudaFuncSetAttribute(post_kernel, cudaFuncAttributeMaxDynamicSharedMemorySize, SMEM_BYTES);
    }

    // fork: CSR build runs concurrently with node-phase GEMMs
    cudaEventRecord(evFork, 0);
    cudaStreamWaitEvent(sB, evFork, 0);
    zero_counts_kernel<<<(NN + 255)/256, 256, 0, sB>>>();
    hist_kernel<<<(EE + 255)/256, 256, 0, sB>>>(dst);
    scan_kernel<<<1, 1024, 0, sB>>>();
    scatter_kernel<<<(EE + 255)/256, 256, 0, sB>>>(src, dst);
    cudaEventRecord(evJoin, sB);

    precompute_kernel<<<128, 128>>>(Wq, bq, Wk, bk);
    node_kernel<<<ROWS/TM, 256, SMEM_BYTES>>>(x, Wp);

    cudaStreamWaitEvent(0, evJoin, 0);
    agg_kernel<<<ROWS/8, 256>>>();
    post_kernel<<<ROWS/TM, 256, SMEM_BYTES>>>(Wv, bv, lng, lnb, out);
}